// round 17
// baseline (speedup 1.0000x reference)
#include <cuda_runtime.h>
#include <stdint.h>

// Problem constants (fixed by the reference)
#define BATCH 4096
#define V     64
#define D     63
#define DEPTH 16
#define WPB   4            // warps (batch rows) per block
#define FULL  0xffffffffu
#define TILE  (V * D)      // 4032 floats = 16128 bytes per (step,row) snapshot

__device__ __forceinline__ unsigned float_to_ordered(float f) {
    unsigned u = __float_as_uint(f);
    return (u & 0x80000000u) ? ~u : (u | 0x80000000u);
}

__device__ __forceinline__ uint32_t smem_u32(const void* p) {
    return (uint32_t)__cvta_generic_to_shared(p);
}

__global__ __launch_bounds__(WPB * 32)
void scn_kernel(const float* __restrict__ inp,
                const float* __restrict__ L,
                const float* __restrict__ visible_fs,
                const float* __restrict__ visible_units,
                const float* __restrict__ biases,
                float* __restrict__ out)
{
    __shared__ __align__(16) float vu_p[TILE + 16]; // visible_units in OUTPUT layout (v*63+d), zero-padded
    __shared__ float Ls[DEPTH][V];                 // L matrix
    __shared__ float hsel_s[WPB][DEPTH][64];       // per-warp stored h_sel vectors (stride-64 rows)
    __shared__ int   ovr_s[WPB][V];                // per-warp: depth of latest override, or -1
    __shared__ float bias_s[DEPTH];
    // ~37.5 KB -> 6 blocks/SM

    const int tid  = threadIdx.x;
    const int wid  = tid >> 5;
    const int lane = tid & 31;

    // ---- block-shared loads ----
    for (int k = tid; k < TILE; k += blockDim.x)
        vu_p[k] = visible_units[k];                // same layout as output tile
    for (int k = tid; k < DEPTH * V; k += blockDim.x)
        Ls[k / V][k % V] = L[k];
    if (tid < DEPTH) bias_s[tid] = biases[tid];
    if (tid < 16)    vu_p[TILE + tid] = 0.0f;      // pad for lane31 second-half reads
    __syncthreads();

    const int b = blockIdx.x * WPB + wid;          // batch row for this warp

    const int v0 = lane;                            // this lane owns v = lane and v = 32+lane
    const int v1 = 32 + lane;

    // ---- init per-row state: w (barycentric weights), f ----
    const float* inp_row = inp + (size_t)b * D;
    float w0 = (v0 == 0) ? 0.0f : inp_row[v0 - 1];
    float w1 = inp_row[v1 - 1];                     // v1-1 in [31,62], valid

    {
        float s = __fadd_rn(w0, w1);
        #pragma unroll
        for (int o = 16; o; o >>= 1) s = __fadd_rn(s, __shfl_xor_sync(FULL, s, o));
        if (lane == 0) w0 = __fsub_rn(1.0f, s);
    }

    float f0 = visible_fs[v0];
    float f1 = visible_fs[v1];

    ovr_s[wid][v0] = -1;
    ovr_s[wid][v1] = -1;
    __syncwarp();

    // ---- output layout: [ out(B) | h_old_all(DEPTH,B,V,D) | h_sel_all(DEPTH,B,D) ] ----
    float* out_scalar = out;
    float* h_old      = out + BATCH;
    float* h_sel_out  = h_old + (size_t)DEPTH * BATCH * TILE;

    const uint32_t vu_sa = smem_u32(vu_p);

    for (int i = 0; i < DEPTH; ++i) {
        float* dst = h_old + ((size_t)i * BATCH + b) * TILE;    // 16-byte aligned tile

        // ---- 1) kick off the bulk snapshot: smem(vu_p) -> gmem tile, async engine ----
        if (lane == 0) {
            asm volatile(
                "cp.async.bulk.global.shared::cta.bulk_group [%0], [%1], %2;"
                :: "l"(dst), "r"(vu_sa), "r"((unsigned)(TILE * 4)) : "memory");
            asm volatile("cp.async.bulk.commit_group;" ::: "memory");
        }

        const float li0 = Ls[i][v0];
        const float li1 = Ls[i][v1];
        const float r0 = __fdiv_rn(1.0f, __fadd_rn(li0, 1e-20f));
        const float r1 = __fdiv_rn(1.0f, __fadd_rn(li1, 1e-20f));

        // ---- 2) argmin of wd = w * fl(1/(Li+1e-20)), first-index tie-break ----
        float wd0 = __fmul_rn(w0, r0);
        float wd1 = __fmul_rn(w1, r1);
        unsigned long long k0 = ((unsigned long long)float_to_ordered(wd0) << 32) | (unsigned)v0;
        unsigned long long k1 = ((unsigned long long)float_to_ordered(wd1) << 32) | (unsigned)v1;
        unsigned long long kk = k0 < k1 ? k0 : k1;
        #pragma unroll
        for (int o = 16; o; o >>= 1) {
            unsigned long long other = __shfl_xor_sync(FULL, kk, o);
            kk = other < kk ? other : kk;
        }
        const int idx = (int)(unsigned)kk;
        unsigned ub = (unsigned)(kk >> 32);
        ub = (ub & 0x80000000u) ? (ub & 0x7fffffffu) : ~ub;
        const float val = __uint_as_float(ub);

        // ---- f_sel = Li . f + bias[i] ----
        float fp = __fmaf_rn(li0, f0, __fmul_rn(li1, f1));
        #pragma unroll
        for (int o = 16; o; o >>= 1) fp = __fadd_rn(fp, __shfl_xor_sync(FULL, fp, o));
        const float f_sel = __fadd_rn(fp, bias_s[i]);

        // ---- w update: single-rounded FMA (measured-correct form) ----
        w0 = __fmaf_rn(-val, li0, w0);
        w1 = __fmaf_rn(-val, li1, w1);
        if (v0 == idx) w0 = val;
        if (v1 == idx) w1 = val;

        // ---- 3) h_sel = Li . h  (smem-only dot; packed-63 reads are conflict-free) ----
        float acc0 = 0.0f, acc1 = 0.0f;
        #pragma unroll 8
        for (int v = 0; v < V; ++v) {
            const float liv = Ls[i][v];
            const int   j   = ovr_s[wid][v];
            const float* src = (j >= 0) ? &hsel_s[wid][j][0] : &vu_p[v * D];
            acc0 = __fmaf_rn(liv, src[lane], acc0);
            acc1 = __fmaf_rn(liv, src[32 + lane], acc1);
        }

        // ---- emit h_sel_all[i][b][:] (independent of the bulk tile) ----
        float* hso = h_sel_out + ((size_t)i * BATCH + b) * D;
        __stcs(&hso[lane], acc0);
        if (lane < 31) __stcs(&hso[32 + lane], acc1);

        // ---- 4) wait for the bulk snapshot, then patch overridden rows ----
        unsigned m0 = __ballot_sync(FULL, ovr_s[wid][v0] >= 0);
        unsigned m1 = __ballot_sync(FULL, ovr_s[wid][v1] >= 0);
        if (lane == 0)
            asm volatile("cp.async.bulk.wait_group 0;" ::: "memory");
        asm volatile("fence.proxy.async;" ::: "memory");
        __syncwarp();

        while (m0) {
            const int v = __ffs(m0) - 1; m0 &= m0 - 1;
            const int j = ovr_s[wid][v];
            const float* src = &hsel_s[wid][j][0];
            __stcs(&dst[v * D + lane], src[lane]);
            if (lane < 31) __stcs(&dst[v * D + 32 + lane], src[32 + lane]);
        }
        while (m1) {
            const int v = 32 + __ffs(m1) - 1; m1 &= m1 - 1;
            const int j = ovr_s[wid][v];
            const float* src = &hsel_s[wid][j][0];
            __stcs(&dst[v * D + lane], src[lane]);
            if (lane < 31) __stcs(&dst[v * D + 32 + lane], src[32 + lane]);
        }

        // ---- 5) state updates: h[idx] <- h_sel (as override), f[idx] <- f_sel ----
        hsel_s[wid][i][lane]      = acc0;
        hsel_s[wid][i][32 + lane] = acc1;   // slot 63: pad, never emitted
        if (v0 == idx) f0 = f_sel;
        if (v1 == idx) f1 = f_sel;
        if (lane == (idx & 31)) ovr_s[wid][idx] = i;
        __syncwarp();
    }

    // ---- out[b] = w . f (exact f32 fma tree) ----
    float p = __fmaf_rn(w0, f0, __fmul_rn(w1, f1));
    #pragma unroll
    for (int o = 16; o; o >>= 1) p = __fadd_rn(p, __shfl_xor_sync(FULL, p, o));
    if (lane == 0) out_scalar[b] = p;
}

extern "C" void kernel_launch(void* const* d_in, const int* in_sizes, int n_in,
                              void* d_out, int out_size) {
    const float* inp         = (const float*)d_in[0];
    const float* L           = (const float*)d_in[1];
    const float* visible_fs  = (const float*)d_in[2];
    const float* vis_units   = (const float*)d_in[3];
    const float* biases      = (const float*)d_in[4];
    float* out = (float*)d_out;

    dim3 grid(BATCH / WPB);
    dim3 block(WPB * 32);
    scn_kernel<<<grid, block>>>(inp, L, visible_fs, vis_units, biases, out);
}